// round 1
// baseline (speedup 1.0000x reference)
#include <cuda_runtime.h>
#include <math.h>

#define NNODE 20000
#define DIM 256
#define HEADS 4
#define NE 100000
#define HC 1024   // HEADS * C, C == DIM

// ---------------- scratch (device globals; no allocation allowed) ----------
__device__ __align__(16) float g_deg[NNODE];           // degree -> dinv
__device__ __align__(16) float g_h[NNODE * DIM];       // f_all @ W_gcn
__device__ __align__(16) float g_x[NNODE * DIM];       // GCN out -> later reused for tf
__device__ __align__(16) float g_q[NNODE * HC];
__device__ __align__(16) float g_k[NNODE * HC];
__device__ __align__(16) float g_v[NNODE * HC];
__device__ __align__(16) float g_skip[NNODE * DIM];
__device__ __align__(16) float g_logits[NE * HEADS];   // logits -> exp values
__device__ __align__(16) float g_m[NNODE * HEADS];
__device__ __align__(16) float g_denom[NNODE * HEADS];
__device__ __align__(16) float g_agg[NNODE * DIM];     // head-averaged attention output

// ---------------- helpers --------------------------------------------------
__device__ __forceinline__ void atomicMaxFloat(float* addr, float val) {
    if (val >= 0.0f) {
        atomicMax((int*)addr, __float_as_int(val));
    } else {
        atomicMin((unsigned int*)addr, (unsigned int)__float_as_int(val));
    }
}

// ---------------- init -----------------------------------------------------
__global__ void k_init() {
    int i = blockIdx.x * blockDim.x + threadIdx.x;
    if (i < NNODE) g_deg[i] = 0.0f;
    if (i < NNODE * HEADS) { g_m[i] = -INFINITY; g_denom[i] = 0.0f; }
    if (i < NNODE * DIM)   { g_x[i] = 0.0f; g_agg[i] = 0.0f; }
}

__global__ void k_deg(const int* __restrict__ dst) {
    int e = blockIdx.x * blockDim.x + threadIdx.x;
    if (e < NE) atomicAdd(&g_deg[dst[e]], 1.0f);
}

__global__ void k_dinv() {
    int i = blockIdx.x * blockDim.x + threadIdx.x;
    if (i < NNODE) {
        float d = g_deg[i] + 1.0f;   // self loop
        g_deg[i] = 1.0f / sqrtf(d);
    }
}

// ---------------- SGEMM ----------------------------------------------------
// C[M,N] = A[M,K] @ op(B) (+bias, relu).  BTRANS=false: B is [K,N] row-major.
// BTRANS=true: B is [N,K] row-major (NT gemm).  bias_mode: 0 none, 1 per-col, 2 per-row.
template <bool BTRANS>
__global__ __launch_bounds__(256) void sgemm(
    const float* __restrict__ A, const float* __restrict__ B,
    const float* __restrict__ bias, float* __restrict__ C,
    int M, int N, int K, int bias_mode, int do_relu)
{
    const int BM = 128, BN = 64, BK = 16;
    __shared__ float As[BK][BM + 4];
    __shared__ float Bs[BK][BN + 4];

    int tid = threadIdx.x;
    int tx = tid & 15;       // 16 col-groups of 4
    int ty = tid >> 4;       // 16 row-groups of 8
    int brow = blockIdx.y * BM;
    int bcol = blockIdx.x * BN;

    float acc[8][4];
#pragma unroll
    for (int i = 0; i < 8; i++)
#pragma unroll
        for (int j = 0; j < 4; j++) acc[i][j] = 0.0f;

    for (int k0 = 0; k0 < K; k0 += BK) {
        // A tile: 128x16, transposed into As. 2 float4 per thread.
#pragma unroll
        for (int t = 0; t < 2; t++) {
            int id = tid * 2 + t;       // 0..511
            int r  = id >> 2;           // 0..127
            int c4 = (id & 3) * 4;      // 0,4,8,12
            float4 v = make_float4(0.f, 0.f, 0.f, 0.f);
            if (brow + r < M)
                v = *(const float4*)&A[(size_t)(brow + r) * K + k0 + c4];
            As[c4 + 0][r] = v.x; As[c4 + 1][r] = v.y;
            As[c4 + 2][r] = v.z; As[c4 + 3][r] = v.w;
        }
        // B tile: 16x64 into Bs. 1 float4 per thread.
        if (!BTRANS) {
            int kr = tid >> 4;          // 0..15
            int c4 = (tid & 15) * 4;    // 0..60
            float4 v = make_float4(0.f, 0.f, 0.f, 0.f);
            if (bcol + c4 < N)          // N always multiple of 4 here
                v = *(const float4*)&B[(size_t)(k0 + kr) * N + bcol + c4];
            Bs[kr][c4 + 0] = v.x; Bs[kr][c4 + 1] = v.y;
            Bs[kr][c4 + 2] = v.z; Bs[kr][c4 + 3] = v.w;
        } else {
            int n   = tid >> 2;         // 0..63
            int kk4 = (tid & 3) * 4;    // 0,4,8,12
            float4 v = make_float4(0.f, 0.f, 0.f, 0.f);
            if (bcol + n < N)
                v = *(const float4*)&B[(size_t)(bcol + n) * K + k0 + kk4];
            Bs[kk4 + 0][n] = v.x; Bs[kk4 + 1][n] = v.y;
            Bs[kk4 + 2][n] = v.z; Bs[kk4 + 3][n] = v.w;
        }
        __syncthreads();

#pragma unroll
        for (int kk = 0; kk < BK; kk++) {
            float a[8], b[4];
#pragma unroll
            for (int i = 0; i < 8; i++) a[i] = As[kk][ty * 8 + i];
#pragma unroll
            for (int j = 0; j < 4; j++) b[j] = Bs[kk][tx * 4 + j];
#pragma unroll
            for (int i = 0; i < 8; i++)
#pragma unroll
                for (int j = 0; j < 4; j++)
                    acc[i][j] = fmaf(a[i], b[j], acc[i][j]);
        }
        __syncthreads();
    }

#pragma unroll
    for (int i = 0; i < 8; i++) {
        int row = brow + ty * 8 + i;
        if (row >= M) continue;
#pragma unroll
        for (int j = 0; j < 4; j++) {
            int col = bcol + tx * 4 + j;
            if (col >= N) continue;
            float v = acc[i][j];
            if (bias_mode == 1) v += bias[col];
            else if (bias_mode == 2) v += bias[row];
            if (do_relu) v = fmaxf(v, 0.0f);
            C[(size_t)row * N + col] = v;
        }
    }
}

// ---------------- GCN edge scatter -----------------------------------------
__global__ void k_gcn_scatter(const int* __restrict__ src, const int* __restrict__ dst) {
    int wid  = (blockIdx.x * blockDim.x + threadIdx.x) >> 5;
    int lane = threadIdx.x & 31;
    if (wid >= NE) return;
    int s = src[wid], d = dst[wid];
    float w = g_deg[s] * g_deg[d];   // holds dinv now
#pragma unroll
    for (int it = 0; it < 2; it++) {
        int c = it * 128 + lane * 4;
        float4 hv = *(const float4*)&g_h[(size_t)s * DIM + c];
        float* o = &g_x[(size_t)d * DIM + c];
        atomicAdd(o + 0, hv.x * w);
        atomicAdd(o + 1, hv.y * w);
        atomicAdd(o + 2, hv.z * w);
        atomicAdd(o + 3, hv.w * w);
    }
}

__global__ void k_gcn_finish(const float* __restrict__ b_gcn) {
    int i = blockIdx.x * blockDim.x + threadIdx.x;
    if (i < NNODE * DIM) {
        float dv = g_deg[i / DIM];
        float v = g_x[i] + g_h[i] * dv * dv + b_gcn[i & (DIM - 1)];
        g_x[i] = fmaxf(v, 0.0f);
    }
}

// ---------------- attention logits + softmax --------------------------------
__global__ void k_logits(const int* __restrict__ src, const int* __restrict__ dst) {
    int wid  = (blockIdx.x * blockDim.x + threadIdx.x) >> 5;
    int lane = threadIdx.x & 31;
    if (wid >= NE * HEADS) return;
    int e = wid >> 2, h = wid & 3;
    int s = src[e], d = dst[e];
    const float* qp = &g_q[(size_t)d * HC + h * DIM];
    const float* kp = &g_k[(size_t)s * HC + h * DIM];
    int c = lane * 8;
    float4 a0 = *(const float4*)(qp + c);
    float4 a1 = *(const float4*)(qp + c + 4);
    float4 b0 = *(const float4*)(kp + c);
    float4 b1 = *(const float4*)(kp + c + 4);
    float sum = a0.x * b0.x + a0.y * b0.y + a0.z * b0.z + a0.w * b0.w
              + a1.x * b1.x + a1.y * b1.y + a1.z * b1.z + a1.w * b1.w;
#pragma unroll
    for (int off = 16; off > 0; off >>= 1)
        sum += __shfl_xor_sync(0xFFFFFFFFu, sum, off);
    if (lane == 0) {
        float l = sum * (1.0f / 16.0f);   // /sqrt(256)
        g_logits[e * HEADS + h] = l;
        atomicMaxFloat(&g_m[d * HEADS + h], l);
    }
}

__global__ void k_expsum(const int* __restrict__ dst) {
    int i = blockIdx.x * blockDim.x + threadIdx.x;
    if (i < NE * HEADS) {
        int e = i >> 2, h = i & 3;
        int d = dst[e];
        float t = __expf(g_logits[i] - g_m[d * HEADS + h]);
        g_logits[i] = t;
        atomicAdd(&g_denom[d * HEADS + h], t);
    }
}

__global__ void k_agg(const int* __restrict__ src, const int* __restrict__ dst) {
    int wid  = (blockIdx.x * blockDim.x + threadIdx.x) >> 5;
    int lane = threadIdx.x & 31;
    if (wid >= NE) return;
    int s = src[wid], d = dst[wid];
    float alpha[HEADS];
#pragma unroll
    for (int h = 0; h < HEADS; h++)
        alpha[h] = g_logits[wid * HEADS + h]
                 / fmaxf(g_denom[d * HEADS + h], 1e-16f) * 0.25f;
#pragma unroll
    for (int it = 0; it < 2; it++) {
        int c = it * 128 + lane * 4;
        float4 acc = make_float4(0.f, 0.f, 0.f, 0.f);
#pragma unroll
        for (int h = 0; h < HEADS; h++) {
            float4 v = *(const float4*)&g_v[(size_t)s * HC + h * DIM + c];
            acc.x = fmaf(alpha[h], v.x, acc.x);
            acc.y = fmaf(alpha[h], v.y, acc.y);
            acc.z = fmaf(alpha[h], v.z, acc.z);
            acc.w = fmaf(alpha[h], v.w, acc.w);
        }
        float* o = &g_agg[(size_t)d * DIM + c];
        atomicAdd(o + 0, acc.x);
        atomicAdd(o + 1, acc.y);
        atomicAdd(o + 2, acc.z);
        atomicAdd(o + 3, acc.w);
    }
}

// ---------------- beta gate -> tf (writes into g_x) -------------------------
__global__ void k_beta(const float* __restrict__ W_beta) {
    int wid  = (blockIdx.x * blockDim.x + threadIdx.x) >> 5;
    int lane = threadIdx.x & 31;
    if (wid >= NNODE) return;
    float o[8], r[8];
    float s = 0.0f;
#pragma unroll
    for (int i = 0; i < 8; i++) {
        int c = lane + i * 32;
        o[i] = g_agg[(size_t)wid * DIM + c];
        r[i] = g_skip[(size_t)wid * DIM + c];
        s += o[i] * W_beta[c] + r[i] * W_beta[DIM + c] + (o[i] - r[i]) * W_beta[2 * DIM + c];
    }
#pragma unroll
    for (int off = 16; off > 0; off >>= 1)
        s += __shfl_xor_sync(0xFFFFFFFFu, s, off);
    float beta = 1.0f / (1.0f + __expf(-s));
#pragma unroll
    for (int i = 0; i < 8; i++) {
        int c = lane + i * 32;
        float tf = beta * r[i] + (1.0f - beta) * o[i];
        g_x[(size_t)wid * DIM + c] = fmaxf(tf, 0.0f);
    }
}

// ---------------- launch ----------------------------------------------------
extern "C" void kernel_launch(void* const* d_in, const int* in_sizes, int n_in,
                              void* d_out, int out_size) {
    const float* f_all  = (const float*)d_in[0];
    const int*   eidx   = (const int*)d_in[1];
    const float* W_gcn  = (const float*)d_in[2];
    const float* b_gcn  = (const float*)d_in[3];
    const float* W_q    = (const float*)d_in[4];
    const float* b_q    = (const float*)d_in[5];
    const float* W_k    = (const float*)d_in[6];
    const float* b_k    = (const float*)d_in[7];
    const float* W_v    = (const float*)d_in[8];
    const float* b_v    = (const float*)d_in[9];
    const float* W_skip = (const float*)d_in[10];
    const float* b_skip = (const float*)d_in[11];
    const float* W_beta = (const float*)d_in[12];
    const float* W_cnn  = (const float*)d_in[13];
    const float* b_cnn  = (const float*)d_in[14];
    float* out = (float*)d_out;

    const int* src = eidx;
    const int* dst = eidx + NE;

    float* d_h    = nullptr; cudaGetSymbolAddress((void**)&d_h,    g_h);
    float* d_x    = nullptr; cudaGetSymbolAddress((void**)&d_x,    g_x);
    float* d_q    = nullptr; cudaGetSymbolAddress((void**)&d_q,    g_q);
    float* d_k    = nullptr; cudaGetSymbolAddress((void**)&d_k,    g_k);
    float* d_v    = nullptr; cudaGetSymbolAddress((void**)&d_v,    g_v);
    float* d_skip = nullptr; cudaGetSymbolAddress((void**)&d_skip, g_skip);

    // init + degree
    k_init<<<(NNODE * DIM + 255) / 256, 256>>>();
    k_deg<<<(NE + 255) / 256, 256>>>(dst);
    k_dinv<<<(NNODE + 255) / 256, 256>>>();

    // GCN: h = f_all @ W_gcn
    {
        dim3 grid((DIM + 63) / 64, (NNODE + 127) / 128);
        sgemm<false><<<grid, 256>>>(f_all, W_gcn, nullptr, d_h, NNODE, DIM, DIM, 0, 0);
    }
    k_gcn_scatter<<<(NE * 32 + 255) / 256, 256>>>(src, dst);
    k_gcn_finish<<<(NNODE * DIM + 255) / 256, 256>>>(b_gcn);

    // QKV + skip projections
    {
        dim3 gq((HC + 63) / 64, (NNODE + 127) / 128);
        sgemm<false><<<gq, 256>>>(d_x, W_q, b_q, d_q, NNODE, HC, DIM, 1, 0);
        sgemm<false><<<gq, 256>>>(d_x, W_k, b_k, d_k, NNODE, HC, DIM, 1, 0);
        sgemm<false><<<gq, 256>>>(d_x, W_v, b_v, d_v, NNODE, HC, DIM, 1, 0);
        dim3 gs((DIM + 63) / 64, (NNODE + 127) / 128);
        sgemm<false><<<gs, 256>>>(d_x, W_skip, b_skip, d_skip, NNODE, DIM, DIM, 1, 0);
    }

    // attention
    k_logits<<<(NE * HEADS * 32 + 255) / 256, 256>>>(src, dst);
    k_expsum<<<(NE * HEADS + 255) / 256, 256>>>(dst);
    k_agg<<<(NE * 32 + 255) / 256, 256>>>(src, dst);

    // gate
    k_beta<<<(NNODE * 32 + 255) / 256, 256>>>(W_beta);

    // final: out[c, n] = sum_d W_cnn[c,d] * tf[n,d] + b_cnn[c]   (NT gemm, per-row bias)
    {
        dim3 grid((NNODE + 63) / 64, (DIM + 127) / 128);
        sgemm<true><<<grid, 256>>>(W_cnn, d_x, b_cnn, out, DIM, NNODE, DIM, 2, 0);
    }
}